// round 12
// baseline (speedup 1.0000x reference)
#include <cuda_runtime.h>
#include <cuda_fp16.h>
#include <math.h>
#include <stdint.h>

#define B_    16
#define N_    8192
#define D_    384
#define DEG_  16
#define K_    8
#define H_    128
#define NODES (B_ * N_)
#define WCOLS 256
#define MTILE 128         // rows per CTA
#define NTILE 128         // cols per CTA (one half)
#define KCH   32
#define NCH   (D_ / KCH)  // 12
#define WSCALE 1024.0f
#define WINV  (1.0f / 1024.0f)

// ---- smem layout (bytes) ----
#define SM_QC     0          // 128 f32
#define SM_W2     512        // 128x8 f32
#define SM_P2     4608       // 128 f32
#define SM_B2     5120       // 8 f32
#define SM_PB2    5152       // 1 f32
#define SM_A      5632       // 3 bufs x 8KB = 24KB
#define SM_B      30208      // 3 bufs x (hi 8KB + lo 8KB) = 48KB
#define SM_TOTAL  79360
#define SM_EPART  5632       // reuse A region post-loop (16KB needed, 24KB avail)

__device__ float g_qc[B_ * WCOLS];
__device__ __half g_WhiT[WCOLS * D_];   // fp16(B*1024) hi, BT[n][k]
__device__ __half g_WloT[WCOLS * D_];   // fp16 residual
__device__ float g_W2[H_ * K_];
__device__ float g_P2[H_];
__device__ float g_b2[K_];
__device__ float g_pb2[1];
__device__ float g_s[NODES * K_];
__device__ float g_factor[NODES];
__device__ float g_amps[NODES * K_];
__device__ float g_bufA[NODES * K_];
__device__ float g_bufB[NODES * K_];
__device__ float g_absum[NODES];
__device__ float g_part[512];

// ---------------- helpers ----------------
__device__ __forceinline__ uint32_t smem_u32(const void* p) {
    uint32_t a;
    asm("{ .reg .u64 t; cvta.to.shared.u64 t, %1; cvt.u32.u64 %0, t; }" : "=r"(a) : "l"(p));
    return a;
}
__device__ __forceinline__ uint32_t pk2h(__half a, __half b) {
    __half2 t(a, b);
    return *reinterpret_cast<uint32_t*>(&t);
}
// paired-row swizzle: two 64B rows per 128B line, granule-XOR by line
__device__ __forceinline__ uint32_t off64(int r, int g) {
    uint32_t line = (uint32_t)(r >> 1);
    uint32_t col = (uint32_t)(((r & 1) << 6) | (g << 4));
    return line * 128 + (col ^ ((line & 7) << 4));
}
__device__ __forceinline__ void cp16(uint32_t dst, const void* src) {
    asm volatile("cp.async.cg.shared.global [%0], [%1], 16;" :: "r"(dst), "l"(src) : "memory");
}
__device__ __forceinline__ void cp_commit() {
    asm volatile("cp.async.commit_group;" ::: "memory");
}
__device__ __forceinline__ void mma_f16(float* d, const uint32_t* a, const uint32_t* b) {
    asm volatile(
        "mma.sync.aligned.m16n8k16.row.col.f32.f16.f16.f32 "
        "{%0,%1,%2,%3}, {%4,%5,%6,%7}, {%8,%9}, {%0,%1,%2,%3};"
        : "+f"(d[0]), "+f"(d[1]), "+f"(d[2]), "+f"(d[3])
        : "r"(a[0]), "r"(a[1]), "r"(a[2]), "r"(a[3]), "r"(b[0]), "r"(b[1]));
}
__device__ __forceinline__ void ldm_x4(uint32_t& r0, uint32_t& r1, uint32_t& r2, uint32_t& r3,
                                       uint32_t addr) {
    asm volatile("ldmatrix.sync.aligned.m8n8.x4.shared.b16 {%0,%1,%2,%3}, [%4];"
                 : "=r"(r0), "=r"(r1), "=r"(r2), "=r"(r3) : "r"(addr));
}

// ---------------- prep kernels ----------------
__global__ void prep_wt(const float* __restrict__ W1, const float* __restrict__ P1) {
    int i = blockIdx.x * blockDim.x + threadIdx.x;   // 256*384
    int n = i / D_;
    int kd = i - n * D_;
    float v = ((n < H_) ? W1[kd * H_ + n] : P1[kd * H_ + (n - H_)]) * WSCALE;
    __half hi = __float2half_rn(v);
    __half lo = __float2half_rn(v - __half2float(hi));
    g_WhiT[i] = hi;
    g_WloT[i] = lo;
}

__global__ void prep_qc(const float* __restrict__ q,
                        const float* __restrict__ W1, const float* __restrict__ b1,
                        const float* __restrict__ P1, const float* __restrict__ pb1) {
    __shared__ float qs[D_];
    int b = blockIdx.x;
    int j = threadIdx.x;
    for (int d = j; d < D_; d += 256) qs[d] = q[b * D_ + d];
    __syncthreads();
    float s;
    const float* w;
    if (j < H_) { s = b1[j];       w = W1 + (size_t)D_ * H_ + j; }
    else        { s = pb1[j - H_]; w = P1 + (size_t)D_ * H_ + (j - H_); }
#pragma unroll 4
    for (int d = 0; d < D_; d++) s = fmaf(qs[d], w[(size_t)d * H_], s);
    g_qc[b * WCOLS + j] = s;
}

__global__ void prep_small(const float* __restrict__ W2, const float* __restrict__ b2,
                           const float* __restrict__ P2, const float* __restrict__ pb2) {
    int i = threadIdx.x;
    if (i < H_ * K_) g_W2[i] = W2[i];
    if (i < H_) g_P2[i] = P2[i];
    if (i < K_) g_b2[i] = b2[i];
    if (i == 0) g_pb2[0] = pb2[0];
}

// ---------------- GEMM: 128x128 tile / CTA, 256 threads, 8 warps (64x32 each),
// 2 CTAs/SM. Triple-buffered, one __syncthreads per chunk, LDG a full chunk ahead.
__global__ __launch_bounds__(256, 2)
void gemm_tc(const float* __restrict__ emb, const int* __restrict__ labels) {
    extern __shared__ char smem[];
    const uint32_t sb = smem_u32(smem);
    const int tid = threadIdx.x;
    const int wid = tid >> 5;
    const int lane = tid & 31;
    const int half = blockIdx.x & 1;
    const int row0 = (blockIdx.x >> 1) * MTILE;
    const int b = row0 >> 13;
    const int nbase = half * NTILE;

    // tables
    if (tid < NTILE) ((float*)(smem + SM_QC))[tid] = g_qc[b * WCOLS + nbase + tid];
#pragma unroll
    for (int j = 0; j < 4; j++)
        ((float*)(smem + SM_W2))[tid * 4 + j] = g_W2[tid * 4 + j];
    if (tid < H_) ((float*)(smem + SM_P2))[tid] = g_P2[tid];
    if (tid < K_) ((float*)(smem + SM_B2))[tid] = g_b2[tid];
    if (tid == 0) *((float*)(smem + SM_PB2)) = g_pb2[0];

    // ---- hoisted B-prefetch addressing (identical to R11; B is per col-half) ----
    const __half* WhiBase = g_WhiT + (size_t)nbase * D_;
    const __half* WloBase = g_WloT + (size_t)nbase * D_;
    const int bn0 = (tid * 2) >> 2, bg0 = (tid * 2) & 3;
    const int bn1 = (tid * 2 + 1) >> 2, bg1 = (tid * 2 + 1) & 3;
    const uint32_t bo0 = off64(bn0, bg0);
    const uint32_t bo1 = off64(bn1, bg1);
    const char* srcH0 = (const char*)(WhiBase + (size_t)bn0 * D_) + bg0 * 16;
    const char* srcH1 = (const char*)(WhiBase + (size_t)bn1 * D_) + bg1 * 16;
    const char* srcL0 = (const char*)(WloBase + (size_t)bn0 * D_) + bg0 * 16;
    const char* srcL1 = (const char*)(WloBase + (size_t)bn1 * D_) + bg1 * 16;

    auto issueB = [&](int c, int buf) {
        uint32_t bhi = sb + SM_B + buf * 16384;
        uint32_t blo = bhi + 8192;
        size_t koff = (size_t)c * KCH * 2;
        cp16(bhi + bo0, srcH0 + koff);
        cp16(bhi + bo1, srcH1 + koff);
        cp16(blo + bo0, srcL0 + koff);
        cp16(blo + bo1, srcL1 + koff);
        cp_commit();
    };

    // ---- A staging: 128 rows, 2 threads/row. ar = tid>>1, aq = tid&1 (16 floats) ----
    const int ar = tid >> 1;
    const int aq = tid & 1;
    const float* abase = emb + (size_t)(row0 + ar) * D_ + aq * 16;
    const uint32_t aSts0 = off64(ar, aq * 2);
    const uint32_t aSts1 = off64(ar, aq * 2 + 1);

    uint32_t pv[8];   // 16 fp16 packed (pre-converted at LDG time)
    auto ldA = [&](int c, uint32_t* p) {
        const float* s = abase + c * KCH;
        float4 v0 = *(const float4*)(s + 0);
        float4 v1 = *(const float4*)(s + 4);
        float4 v2 = *(const float4*)(s + 8);
        float4 v3 = *(const float4*)(s + 12);
        p[0] = pk2h(__float2half_rn(v0.x), __float2half_rn(v0.y));
        p[1] = pk2h(__float2half_rn(v0.z), __float2half_rn(v0.w));
        p[2] = pk2h(__float2half_rn(v1.x), __float2half_rn(v1.y));
        p[3] = pk2h(__float2half_rn(v1.z), __float2half_rn(v1.w));
        p[4] = pk2h(__float2half_rn(v2.x), __float2half_rn(v2.y));
        p[5] = pk2h(__float2half_rn(v2.z), __float2half_rn(v2.w));
        p[6] = pk2h(__float2half_rn(v3.x), __float2half_rn(v3.y));
        p[7] = pk2h(__float2half_rn(v3.z), __float2half_rn(v3.w));
    };
    auto stsA = [&](const uint32_t* p, int buf) {
        uint32_t ab = sb + SM_A + buf * 8192;
        asm volatile("st.shared.v4.b32 [%0], {%1,%2,%3,%4};" :: "r"(ab + aSts0),
                     "r"(p[0]), "r"(p[1]), "r"(p[2]), "r"(p[3]) : "memory");
        asm volatile("st.shared.v4.b32 [%0], {%1,%2,%3,%4};" :: "r"(ab + aSts1),
                     "r"(p[4]), "r"(p[5]), "r"(p[6]), "r"(p[7]) : "memory");
    };

    // prologue: B0->buf0, B1->buf1; A0->smem buf0; A1 in regs
    issueB(0, 0);
    issueB(1, 1);
    ldA(0, pv);
    stsA(pv, 0);
    ldA(1, pv);

    // accumulators: per-warp 64x32 -> acc[4 mf][4 nf][4]
    float acc[4][4][4];
#pragma unroll
    for (int i = 0; i < 4; i++)
#pragma unroll
        for (int j = 0; j < 4; j++)
#pragma unroll
            for (int k = 0; k < 4; k++) acc[i][j][k] = 0.f;

    const int wm = wid >> 2;        // 0..1: 64-row band
    const int wn = wid & 3;         // 0..3: 32-col slice
    const int m0 = wm * 64;
    const int n0w = wn * 32;
    const int g4 = lane >> 2;
    const int t4 = lane & 3;

    // per-lane ldmatrix offsets
    const int lr = lane & 7;
    const int sel = lane >> 3;
    uint32_t aOff[4][2], bOff[2][2];
#pragma unroll
    for (int mf = 0; mf < 4; mf++) {
        int rA = m0 + mf * 16 + lr + ((sel & 1) ? 8 : 0);
#pragma unroll
        for (int ks = 0; ks < 2; ks++)
            aOff[mf][ks] = off64(rA, ks * 2 + ((sel >> 1) & 1));
    }
#pragma unroll
    for (int nfp = 0; nfp < 2; nfp++) {
        int rB = n0w + nfp * 16 + ((sel >> 1) ? 8 : 0) + lr;
#pragma unroll
        for (int ks = 0; ks < 2; ks++)
            bOff[nfp][ks] = off64(rB, ks * 2 + (sel & 1));
    }

    int bufc = 0;   // c % 3
    for (int c = 0; c < NCH; c++) {
        if (c == NCH - 1) asm volatile("cp.async.wait_group 0;" ::: "memory");
        else              asm volatile("cp.async.wait_group 1;" ::: "memory");
        __syncthreads();    // publish stsA(A(c)) + B(c); all warps done with mma(c-1)

        {
            int buf2 = bufc + 2; if (buf2 >= 3) buf2 -= 3;
            int buf1 = bufc + 1; if (buf1 >= 3) buf1 -= 3;
            if (c + 2 < NCH) issueB(c + 2, buf2);       // safe: mma(c-1) reads done
            if (c + 1 < NCH) stsA(pv, buf1);            // safe: mma(c-2) reads done
            if (c + 2 < NCH) ldA(c + 2, pv);            // full-chunk slack to next stsA
        }

        const uint32_t AB   = sb + SM_A + bufc * 8192;
        const uint32_t BhiB = sb + SM_B + bufc * 16384;
        const uint32_t BloB = BhiB + 8192;

#pragma unroll
        for (int ks = 0; ks < 2; ks++) {
            uint32_t ah[4][4], bh[4][2], bl[4][2];
#pragma unroll
            for (int nfp = 0; nfp < 2; nfp++)
                ldm_x4(bh[nfp * 2][0], bh[nfp * 2][1], bh[nfp * 2 + 1][0], bh[nfp * 2 + 1][1],
                       BhiB + bOff[nfp][ks]);
#pragma unroll
            for (int mf = 0; mf < 4; mf++)
                ldm_x4(ah[mf][0], ah[mf][1], ah[mf][2], ah[mf][3], AB + aOff[mf][ks]);
#pragma unroll
            for (int mf = 0; mf < 4; mf++)
#pragma unroll
                for (int nf = 0; nf < 4; nf++)
                    mma_f16(acc[mf][nf], ah[mf], bh[nf]);
#pragma unroll
            for (int nfp = 0; nfp < 2; nfp++)
                ldm_x4(bl[nfp * 2][0], bl[nfp * 2][1], bl[nfp * 2 + 1][0], bl[nfp * 2 + 1][1],
                       BloB + bOff[nfp][ks]);
#pragma unroll
            for (int mf = 0; mf < 4; mf++)
#pragma unroll
                for (int nf = 0; nf < 4; nf++)
                    mma_f16(acc[mf][nf], ah[mf], bl[nf]);
        }
        if (++bufc == 3) bufc = 0;
    }
    __syncthreads();    // protect EPART reuse of A region

    // ---------------- epilogue (per col-half); acc scaled by 2^-10 ----------------
    const float* qcs = (const float*)(smem + SM_QC);
    const float* W2s = (const float*)(smem + SM_W2);
    const float* P2s = (const float*)(smem + SM_P2);
    float* epart = (float*)(smem + SM_EPART);

    if (half == 0) {
#pragma unroll
        for (int mf = 0; mf < 4; mf++) {
#pragma unroll
            for (int rg = 0; rg < 2; rg++) {
                int rowl = m0 + mf * 16 + g4 + rg * 8;
                float p[8] = {0.f, 0.f, 0.f, 0.f, 0.f, 0.f, 0.f, 0.f};
#pragma unroll
                for (int nf = 0; nf < 4; nf++) {
#pragma unroll
                    for (int cp = 0; cp < 2; cp++) {
                        int lc = n0w + nf * 8 + t4 * 2 + cp;
                        float hv = fmaxf(fmaf(acc[mf][nf][rg * 2 + cp], WINV, qcs[lc]), 0.f);
                        const float* w = W2s + lc * 8;
#pragma unroll
                        for (int k = 0; k < 8; k++) p[k] = fmaf(hv, w[k], p[k]);
                    }
                }
#pragma unroll
                for (int k = 0; k < 8; k++) {
                    p[k] += __shfl_xor_sync(0xffffffffu, p[k], 1);
                    p[k] += __shfl_xor_sync(0xffffffffu, p[k], 2);
                }
                if (t4 == 0) {
#pragma unroll
                    for (int k = 0; k < 8; k++)
                        epart[((size_t)wn * 128 + rowl) * 8 + k] = p[k];
                }
            }
        }
        __syncthreads();
        const float* b2s = (const float*)(smem + SM_B2);
        for (int t = tid; t < 128 * 8; t += 256) {
            int r = t >> 3, k = t & 7;
            float s = epart[(0 * 128 + r) * 8 + k] + epart[(1 * 128 + r) * 8 + k]
                    + epart[(2 * 128 + r) * 8 + k] + epart[(3 * 128 + r) * 8 + k];
            g_s[(size_t)(row0 + r) * K_ + k] = s + b2s[k];
        }
    } else {
#pragma unroll
        for (int mf = 0; mf < 4; mf++) {
#pragma unroll
            for (int rg = 0; rg < 2; rg++) {
                int rowl = m0 + mf * 16 + g4 + rg * 8;
                float p8 = 0.f;
#pragma unroll
                for (int nf = 0; nf < 4; nf++) {
#pragma unroll
                    for (int cp = 0; cp < 2; cp++) {
                        int lc = n0w + nf * 8 + t4 * 2 + cp;
                        float hv = fmaxf(fmaf(acc[mf][nf][rg * 2 + cp], WINV, qcs[lc]), 0.f);
                        p8 = fmaf(hv, P2s[lc], p8);
                    }
                }
                p8 += __shfl_xor_sync(0xffffffffu, p8, 1);
                p8 += __shfl_xor_sync(0xffffffffu, p8, 2);
                if (t4 == 0) epart[(size_t)wn * 128 + rowl] = p8;
            }
        }
        __syncthreads();
        if (tid < 128) {
            float logit = epart[0 * 128 + tid] + epart[1 * 128 + tid]
                        + epart[2 * 128 + tid] + epart[3 * 128 + tid]
                        + *((const float*)(smem + SM_PB2));
            int row = row0 + tid;
            float factor = 1.f + 1.f / (1.f + expf(-logit)) + (float)labels[row];
            g_factor[row] = factor;
        }
    }
}

// ---------------- amps = s * factor ----------------
__global__ void finalize_amps() {
    int node = blockIdx.x * blockDim.x + threadIdx.x;
    float f = g_factor[node];
    const float4* s = (const float4*)(g_s + (size_t)node * K_);
    float4 s0 = s[0], s1 = s[1];
    float4* o = (float4*)(g_amps + (size_t)node * K_);
    o[0] = make_float4(s0.x * f, s0.y * f, s0.z * f, s0.w * f);
    o[1] = make_float4(s1.x * f, s1.y * f, s1.z * f, s1.w * f);
}

// ---------------- diffusion ----------------
__device__ __forceinline__ void gather16(const float4* __restrict__ base,
                                         const int4* __restrict__ nb,
                                         float4& s0, float4& s1) {
    s0 = make_float4(0.f, 0.f, 0.f, 0.f);
    s1 = make_float4(0.f, 0.f, 0.f, 0.f);
#pragma unroll
    for (int j = 0; j < 4; j++) {
        int4 id = nb[j];
        const float4* p;
        float4 v;
        p = base + (size_t)id.x * 2;
        v = p[0]; s0.x += v.x; s0.y += v.y; s0.z += v.z; s0.w += v.w;
        v = p[1]; s1.x += v.x; s1.y += v.y; s1.z += v.z; s1.w += v.w;
        p = base + (size_t)id.y * 2;
        v = p[0]; s0.x += v.x; s0.y += v.y; s0.z += v.z; s0.w += v.w;
        v = p[1]; s1.x += v.x; s1.y += v.y; s1.z += v.z; s1.w += v.w;
        p = base + (size_t)id.z * 2;
        v = p[0]; s0.x += v.x; s0.y += v.y; s0.z += v.z; s0.w += v.w;
        v = p[1]; s1.x += v.x; s1.y += v.y; s1.z += v.z; s1.w += v.w;
        p = base + (size_t)id.w * 2;
        v = p[0]; s0.x += v.x; s0.y += v.y; s0.z += v.z; s0.w += v.w;
        v = p[1]; s1.x += v.x; s1.y += v.y; s1.z += v.z; s1.w += v.w;
    }
}

__device__ __forceinline__ void spmm_body(const float* __restrict__ in,
                                          float* __restrict__ out,
                                          const int* __restrict__ neighbors) {
    int node = blockIdx.x * blockDim.x + threadIdx.x;
    int b = node >> 13;
    const int4* nb = (const int4*)(neighbors + (size_t)node * DEG_);
    const float4* base = (const float4*)(in + (size_t)b * N_ * K_);
    float4 s0, s1;
    gather16(base, nb, s0, s1);
    const float4* am = (const float4*)(g_amps + (size_t)node * K_);
    float4 a0 = am[0], a1 = am[1];
    float4* o = (float4*)(out + (size_t)node * K_);
    o[0] = make_float4(s0.x * a0.x, s0.y * a0.y, s0.z * a0.z, s0.w * a0.w);
    o[1] = make_float4(s1.x * a1.x, s1.y * a1.y, s1.z * a1.z, s1.w * a1.w);
}

__global__ void spmm_step1(const int* __restrict__ neighbors) { spmm_body(g_amps, g_bufA, neighbors); }
__global__ void spmm_step2(const int* __restrict__ neighbors) { spmm_body(g_bufA, g_bufB, neighbors); }

__global__ void spmm_final(const int* __restrict__ neighbors) {
    int node = blockIdx.x * blockDim.x + threadIdx.x;
    int b = node >> 13;
    const int4* nb = (const int4*)(neighbors + (size_t)node * DEG_);
    const float4* base = (const float4*)(g_bufB + (size_t)b * N_ * K_);
    float4 s0, s1;
    gather16(base, nb, s0, s1);
    float absum = fabsf(s0.x) + fabsf(s0.y) + fabsf(s0.z) + fabsf(s0.w)
                + fabsf(s1.x) + fabsf(s1.y) + fabsf(s1.z) + fabsf(s1.w);
    float ss = s0.x * s0.x + s0.y * s0.y + s0.z * s0.z + s0.w * s0.w
             + s1.x * s1.x + s1.y * s1.y + s1.z * s1.z + s1.w * s1.w;
    g_absum[node] = absum;

    __shared__ float red[256];
    int t = threadIdx.x;
    red[t] = ss;
    __syncthreads();
#pragma unroll
    for (int s = 128; s > 0; s >>= 1) {
        if (t < s) red[t] += red[t + s];
        __syncthreads();
    }
    if (t == 0) g_part[blockIdx.x] = red[0];
}

__global__ void finalize(float* __restrict__ out) {
    __shared__ float ssum;
    int node = blockIdx.x * blockDim.x + threadIdx.x;
    int b = node >> 13;
    if (threadIdx.x < 32) {
        float s = g_part[b * 32 + threadIdx.x];
#pragma unroll
        for (int off = 16; off > 0; off >>= 1)
            s += __shfl_xor_sync(0xffffffffu, s, off);
        if (threadIdx.x == 0) ssum = s;
    }
    __syncthreads();
    float ss = ssum;
    float scale = (ss > 0.f) ? rsqrtf(ss) : 1.f;
    out[node] = g_absum[node] * scale;
}

// ---------------- launch ----------------
extern "C" void kernel_launch(void* const* d_in, const int* in_sizes, int n_in,
                              void* d_out, int out_size) {
    const float* q_embs    = (const float*)d_in[0];
    const float* emb       = (const float*)d_in[1];
    const int*   neighbors = (const int*)d_in[2];
    const int*   labels    = (const int*)d_in[3];
    const float* W1        = (const float*)d_in[4];
    const float* b1        = (const float*)d_in[5];
    const float* W2        = (const float*)d_in[6];
    const float* b2        = (const float*)d_in[7];
    const float* P1        = (const float*)d_in[8];
    const float* pb1       = (const float*)d_in[9];
    const float* P2        = (const float*)d_in[10];
    const float* pb2       = (const float*)d_in[11];
    float* out = (float*)d_out;

    cudaFuncSetAttribute(gemm_tc, cudaFuncAttributeMaxDynamicSharedMemorySize, SM_TOTAL);

    prep_wt<<<(WCOLS * D_) / 256, 256>>>(W1, P1);
    prep_qc<<<B_, 256>>>(q_embs, W1, b1, P1, pb1);
    prep_small<<<1, 1024>>>(W2, b2, P2, pb2);
    gemm_tc<<<(NODES / MTILE) * 2, 256, SM_TOTAL>>>(emb, labels);
    finalize_amps<<<NODES / 256, 256>>>();
    spmm_step1<<<NODES / 256, 256>>>(neighbors);
    spmm_step2<<<NODES / 256, 256>>>(neighbors);
    spmm_final<<<NODES / 256, 256>>>(neighbors);
    finalize<<<NODES / 256, 256>>>(out);
}

// round 13
// speedup vs baseline: 1.2982x; 1.2982x over previous
#include <cuda_runtime.h>
#include <cuda_fp16.h>
#include <math.h>
#include <stdint.h>

#define B_    16
#define N_    8192
#define D_    384
#define DEG_  16
#define K_    8
#define H_    128
#define NODES (B_ * N_)
#define WCOLS 256
#define MTILE 64          // rows per CTA
#define NTILE 128         // cols per CTA (one half)
#define KCH   32
#define NCH   (D_ / KCH)  // 12

// ---- smem layout (bytes) ----
#define SM_QC     0          // 128 f32
#define SM_W2     512        // 128x8 f32
#define SM_P2     4608       // 128 f32
#define SM_B2     5120       // 8 f32
#define SM_PB2    5152       // 1 f32
#define SM_A      5632       // 3 bufs x 4KB = 12KB
#define SM_B      17920      // 3 bufs x 8KB = 24KB
#define SM_TOTAL  42496
#define SM_EPART  5632       // reuse A region post-loop (8KB needed, 12KB avail)

__device__ float g_qc[B_ * WCOLS];
__device__ __half g_WT[WCOLS * D_];     // fp16 fused weights, BT[n][k]
__device__ float g_W2[H_ * K_];
__device__ float g_P2[H_];
__device__ float g_b2[K_];
__device__ float g_pb2[1];
__device__ float g_s[NODES * K_];
__device__ float g_factor[NODES];
__device__ float g_amps[NODES * K_];
__device__ float g_bufA[NODES * K_];
__device__ float g_bufB[NODES * K_];
__device__ float g_absum[NODES];
__device__ float g_part[512];

// ---------------- helpers ----------------
__device__ __forceinline__ uint32_t smem_u32(const void* p) {
    uint32_t a;
    asm("{ .reg .u64 t; cvta.to.shared.u64 t, %1; cvt.u32.u64 %0, t; }" : "=r"(a) : "l"(p));
    return a;
}
__device__ __forceinline__ uint32_t pk2h(__half a, __half b) {
    __half2 t(a, b);
    return *reinterpret_cast<uint32_t*>(&t);
}
// paired-row swizzle: two 64B rows per 128B line, granule-XOR by line
__device__ __forceinline__ uint32_t off64(int r, int g) {
    uint32_t line = (uint32_t)(r >> 1);
    uint32_t col = (uint32_t)(((r & 1) << 6) | (g << 4));
    return line * 128 + (col ^ ((line & 7) << 4));
}
__device__ __forceinline__ void cp16(uint32_t dst, const void* src) {
    asm volatile("cp.async.cg.shared.global [%0], [%1], 16;" :: "r"(dst), "l"(src) : "memory");
}
__device__ __forceinline__ void cp_commit() {
    asm volatile("cp.async.commit_group;" ::: "memory");
}
__device__ __forceinline__ void mma_f16(float* d, const uint32_t* a, const uint32_t* b) {
    asm volatile(
        "mma.sync.aligned.m16n8k16.row.col.f32.f16.f16.f32 "
        "{%0,%1,%2,%3}, {%4,%5,%6,%7}, {%8,%9}, {%0,%1,%2,%3};"
        : "+f"(d[0]), "+f"(d[1]), "+f"(d[2]), "+f"(d[3])
        : "r"(a[0]), "r"(a[1]), "r"(a[2]), "r"(a[3]), "r"(b[0]), "r"(b[1]));
}
__device__ __forceinline__ void ldm_x4(uint32_t& r0, uint32_t& r1, uint32_t& r2, uint32_t& r3,
                                       uint32_t addr) {
    asm volatile("ldmatrix.sync.aligned.m8n8.x4.shared.b16 {%0,%1,%2,%3}, [%4];"
                 : "=r"(r0), "=r"(r1), "=r"(r2), "=r"(r3) : "r"(addr));
}

// ---------------- prep kernels ----------------
__global__ void prep_wt(const float* __restrict__ W1, const float* __restrict__ P1) {
    int i = blockIdx.x * blockDim.x + threadIdx.x;   // 256*384
    int n = i / D_;
    int kd = i - n * D_;
    float v = (n < H_) ? W1[kd * H_ + n] : P1[kd * H_ + (n - H_)];
    g_WT[i] = __float2half_rn(v);
}

__global__ void prep_qc(const float* __restrict__ q,
                        const float* __restrict__ W1, const float* __restrict__ b1,
                        const float* __restrict__ P1, const float* __restrict__ pb1) {
    __shared__ float qs[D_];
    int b = blockIdx.x;
    int j = threadIdx.x;
    for (int d = j; d < D_; d += 256) qs[d] = q[b * D_ + d];
    __syncthreads();
    float s;
    const float* w;
    if (j < H_) { s = b1[j];       w = W1 + (size_t)D_ * H_ + j; }
    else        { s = pb1[j - H_]; w = P1 + (size_t)D_ * H_ + (j - H_); }
#pragma unroll 4
    for (int d = 0; d < D_; d++) s = fmaf(qs[d], w[(size_t)d * H_], s);
    g_qc[b * WCOLS + j] = s;
}

__global__ void prep_small(const float* __restrict__ W2, const float* __restrict__ b2,
                           const float* __restrict__ P2, const float* __restrict__ pb2) {
    int i = threadIdx.x;
    if (i < H_ * K_) g_W2[i] = W2[i];
    if (i < H_) g_P2[i] = P2[i];
    if (i < K_) g_b2[i] = b2[i];
    if (i == 0) g_pb2[0] = pb2[0];
}

// ---------------- GEMM: 64x128 tile / CTA, 256 threads, 8 warps, 3 CTAs/SM ----
// SINGLE-PASS fp16. Triple-buffered, one __syncthreads/chunk, LDG a chunk ahead.
__global__ __launch_bounds__(256, 3)
void gemm_tc(const float* __restrict__ emb, const int* __restrict__ labels) {
    extern __shared__ char smem[];
    const uint32_t sb = smem_u32(smem);
    const int tid = threadIdx.x;
    const int wid = tid >> 5;
    const int lane = tid & 31;
    const int half = blockIdx.x & 1;
    const int row0 = (blockIdx.x >> 1) * MTILE;
    const int b = row0 >> 13;
    const int nbase = half * NTILE;

    // tables
    if (tid < NTILE) ((float*)(smem + SM_QC))[tid] = g_qc[b * WCOLS + nbase + tid];
#pragma unroll
    for (int j = 0; j < 4; j++)
        ((float*)(smem + SM_W2))[tid * 4 + j] = g_W2[tid * 4 + j];
    if (tid < H_) ((float*)(smem + SM_P2))[tid] = g_P2[tid];
    if (tid < K_) ((float*)(smem + SM_B2))[tid] = g_b2[tid];
    if (tid == 0) *((float*)(smem + SM_PB2)) = g_pb2[0];

    // ---- hoisted B-prefetch addressing ----
    const __half* WBase = g_WT + (size_t)nbase * D_;
    const int bn0 = (tid * 2) >> 2, bg0 = (tid * 2) & 3;
    const int bn1 = (tid * 2 + 1) >> 2, bg1 = (tid * 2 + 1) & 3;
    const uint32_t bo0 = off64(bn0, bg0);
    const uint32_t bo1 = off64(bn1, bg1);
    const char* src0 = (const char*)(WBase + (size_t)bn0 * D_) + bg0 * 16;
    const char* src1 = (const char*)(WBase + (size_t)bn1 * D_) + bg1 * 16;

    auto issueB = [&](int c, int buf) {
        uint32_t bb = sb + SM_B + buf * 8192;
        size_t koff = (size_t)c * KCH * 2;
        cp16(bb + bo0, src0 + koff);
        cp16(bb + bo1, src1 + koff);
        cp_commit();
    };

    // A staging
    const int ar = tid >> 2;
    const int aq = tid & 3;
    const float* abase = emb + (size_t)(row0 + ar) * D_ + aq * 8;
    const uint32_t aSts = off64(ar, aq);

    auto stsA = [&](const float4& v0, const float4& v1, int buf) {
        uint32_t ab = sb + SM_A + buf * 4096;
        uint32_t p0 = pk2h(__float2half_rn(v0.x), __float2half_rn(v0.y));
        uint32_t p1 = pk2h(__float2half_rn(v0.z), __float2half_rn(v0.w));
        uint32_t p2 = pk2h(__float2half_rn(v1.x), __float2half_rn(v1.y));
        uint32_t p3 = pk2h(__float2half_rn(v1.z), __float2half_rn(v1.w));
        asm volatile("st.shared.v4.b32 [%0], {%1,%2,%3,%4};" :: "r"(ab + aSts),
                     "r"(p0), "r"(p1), "r"(p2), "r"(p3) : "memory");
    };

    // prologue
    issueB(0, 0);
    issueB(1, 1);
    float4 pv0 = *(const float4*)(abase + 0);
    float4 pv1 = *(const float4*)(abase + 4);
    stsA(pv0, pv1, 0);
    pv0 = *(const float4*)(abase + KCH + 0);
    pv1 = *(const float4*)(abase + KCH + 4);

    // accumulators: per-warp 32x32
    float acc[2][4][4];
#pragma unroll
    for (int i = 0; i < 2; i++)
#pragma unroll
        for (int j = 0; j < 4; j++)
#pragma unroll
            for (int k = 0; k < 4; k++) acc[i][j][k] = 0.f;

    const int wm = wid >> 2;
    const int wn = wid & 3;
    const int m0 = wm * 32;
    const int n0w = wn * 32;
    const int g4 = lane >> 2;
    const int t4 = lane & 3;

    // per-lane ldmatrix offsets
    const int lr = lane & 7;
    const int sel = lane >> 3;
    uint32_t aOff[2][2], bOff[2][2];
#pragma unroll
    for (int mf = 0; mf < 2; mf++) {
        int rA = m0 + mf * 16 + lr + ((sel & 1) ? 8 : 0);
#pragma unroll
        for (int ks = 0; ks < 2; ks++)
            aOff[mf][ks] = off64(rA, ks * 2 + ((sel >> 1) & 1));
    }
#pragma unroll
    for (int nfp = 0; nfp < 2; nfp++) {
        int rB = n0w + nfp * 16 + ((sel >> 1) ? 8 : 0) + lr;
#pragma unroll
        for (int ks = 0; ks < 2; ks++)
            bOff[nfp][ks] = off64(rB, ks * 2 + (sel & 1));
    }

    int bufc = 0;   // c % 3
    for (int c = 0; c < NCH; c++) {
        if (c == NCH - 1) asm volatile("cp.async.wait_group 0;" ::: "memory");
        else              asm volatile("cp.async.wait_group 1;" ::: "memory");
        __syncthreads();    // publish stsA(A(c)) + B(c); all warps done with mma(c-1)

        {
            int buf2 = bufc + 2; if (buf2 >= 3) buf2 -= 3;
            int buf1 = bufc + 1; if (buf1 >= 3) buf1 -= 3;
            if (c + 2 < NCH) issueB(c + 2, buf2);
            if (c + 1 < NCH) stsA(pv0, pv1, buf1);
            if (c + 2 < NCH) {
                const float* nb = abase + (c + 2) * KCH;
                pv0 = *(const float4*)(nb + 0);
                pv1 = *(const float4*)(nb + 4);
            }
        }

        const uint32_t AB = sb + SM_A + bufc * 4096;
        const uint32_t BB = sb + SM_B + bufc * 8192;

#pragma unroll
        for (int ks = 0; ks < 2; ks++) {
            uint32_t ah[2][4], bh[4][2];
#pragma unroll
            for (int nfp = 0; nfp < 2; nfp++)
                ldm_x4(bh[nfp * 2][0], bh[nfp * 2][1], bh[nfp * 2 + 1][0], bh[nfp * 2 + 1][1],
                       BB + bOff[nfp][ks]);
#pragma unroll
            for (int mf = 0; mf < 2; mf++)
                ldm_x4(ah[mf][0], ah[mf][1], ah[mf][2], ah[mf][3], AB + aOff[mf][ks]);
#pragma unroll
            for (int mf = 0; mf < 2; mf++)
#pragma unroll
                for (int nf = 0; nf < 4; nf++)
                    mma_f16(acc[mf][nf], ah[mf], bh[nf]);
        }
        if (++bufc == 3) bufc = 0;
    }
    __syncthreads();    // protect EPART reuse of A region

    // ---------------- epilogue ----------------
    const float* qcs = (const float*)(smem + SM_QC);
    const float* W2s = (const float*)(smem + SM_W2);
    const float* P2s = (const float*)(smem + SM_P2);
    float* epart = (float*)(smem + SM_EPART);

    if (half == 0) {
#pragma unroll
        for (int mf = 0; mf < 2; mf++) {
#pragma unroll
            for (int rg = 0; rg < 2; rg++) {
                int rowl = m0 + mf * 16 + g4 + rg * 8;
                float p[8] = {0.f, 0.f, 0.f, 0.f, 0.f, 0.f, 0.f, 0.f};
#pragma unroll
                for (int nf = 0; nf < 4; nf++) {
#pragma unroll
                    for (int cp = 0; cp < 2; cp++) {
                        int lc = n0w + nf * 8 + t4 * 2 + cp;
                        float hv = fmaxf(acc[mf][nf][rg * 2 + cp] + qcs[lc], 0.f);
                        const float* w = W2s + lc * 8;
#pragma unroll
                        for (int k = 0; k < 8; k++) p[k] = fmaf(hv, w[k], p[k]);
                    }
                }
#pragma unroll
                for (int k = 0; k < 8; k++) {
                    p[k] += __shfl_xor_sync(0xffffffffu, p[k], 1);
                    p[k] += __shfl_xor_sync(0xffffffffu, p[k], 2);
                }
                if (t4 == 0) {
#pragma unroll
                    for (int k = 0; k < 8; k++)
                        epart[((size_t)wn * 64 + rowl) * 8 + k] = p[k];
                }
            }
        }
        __syncthreads();
        const float* b2s = (const float*)(smem + SM_B2);
        for (int t = tid; t < 64 * 8; t += 256) {
            int r = t >> 3, k = t & 7;
            float s = epart[(0 * 64 + r) * 8 + k] + epart[(1 * 64 + r) * 8 + k]
                    + epart[(2 * 64 + r) * 8 + k] + epart[(3 * 64 + r) * 8 + k];
            g_s[(size_t)(row0 + r) * K_ + k] = s + b2s[k];
        }
    } else {
#pragma unroll
        for (int mf = 0; mf < 2; mf++) {
#pragma unroll
            for (int rg = 0; rg < 2; rg++) {
                int rowl = m0 + mf * 16 + g4 + rg * 8;
                float p8 = 0.f;
#pragma unroll
                for (int nf = 0; nf < 4; nf++) {
#pragma unroll
                    for (int cp = 0; cp < 2; cp++) {
                        int lc = n0w + nf * 8 + t4 * 2 + cp;
                        float hv = fmaxf(acc[mf][nf][rg * 2 + cp] + qcs[lc], 0.f);
                        p8 = fmaf(hv, P2s[lc], p8);
                    }
                }
                p8 += __shfl_xor_sync(0xffffffffu, p8, 1);
                p8 += __shfl_xor_sync(0xffffffffu, p8, 2);
                if (t4 == 0) epart[(size_t)wn * 64 + rowl] = p8;
            }
        }
        __syncthreads();
        if (tid < 64) {
            float logit = epart[0 * 64 + tid] + epart[1 * 64 + tid]
                        + epart[2 * 64 + tid] + epart[3 * 64 + tid]
                        + *((const float*)(smem + SM_PB2));
            int row = row0 + tid;
            float factor = 1.f + 1.f / (1.f + expf(-logit)) + (float)labels[row];
            g_factor[row] = factor;
        }
    }
}

// ---------------- amps = s * factor ----------------
__global__ void finalize_amps() {
    int node = blockIdx.x * blockDim.x + threadIdx.x;
    float f = g_factor[node];
    const float4* s = (const float4*)(g_s + (size_t)node * K_);
    float4 s0 = s[0], s1 = s[1];
    float4* o = (float4*)(g_amps + (size_t)node * K_);
    o[0] = make_float4(s0.x * f, s0.y * f, s0.z * f, s0.w * f);
    o[1] = make_float4(s1.x * f, s1.y * f, s1.z * f, s1.w * f);
}

// ---------------- diffusion ----------------
__device__ __forceinline__ void gather16(const float4* __restrict__ base,
                                         const int4* __restrict__ nb,
                                         float4& s0, float4& s1) {
    s0 = make_float4(0.f, 0.f, 0.f, 0.f);
    s1 = make_float4(0.f, 0.f, 0.f, 0.f);
#pragma unroll
    for (int j = 0; j < 4; j++) {
        int4 id = nb[j];
        const float4* p;
        float4 v;
        p = base + (size_t)id.x * 2;
        v = p[0]; s0.x += v.x; s0.y += v.y; s0.z += v.z; s0.w += v.w;
        v = p[1]; s1.x += v.x; s1.y += v.y; s1.z += v.z; s1.w += v.w;
        p = base + (size_t)id.y * 2;
        v = p[0]; s0.x += v.x; s0.y += v.y; s0.z += v.z; s0.w += v.w;
        v = p[1]; s1.x += v.x; s1.y += v.y; s1.z += v.z; s1.w += v.w;
        p = base + (size_t)id.z * 2;
        v = p[0]; s0.x += v.x; s0.y += v.y; s0.z += v.z; s0.w += v.w;
        v = p[1]; s1.x += v.x; s1.y += v.y; s1.z += v.z; s1.w += v.w;
        p = base + (size_t)id.w * 2;
        v = p[0]; s0.x += v.x; s0.y += v.y; s0.z += v.z; s0.w += v.w;
        v = p[1]; s1.x += v.x; s1.y += v.y; s1.z += v.z; s1.w += v.w;
    }
}

__device__ __forceinline__ void spmm_body(const float* __restrict__ in,
                                          float* __restrict__ out,
                                          const int* __restrict__ neighbors) {
    int node = blockIdx.x * blockDim.x + threadIdx.x;
    int b = node >> 13;
    const int4* nb = (const int4*)(neighbors + (size_t)node * DEG_);
    const float4* base = (const float4*)(in + (size_t)b * N_ * K_);
    float4 s0, s1;
    gather16(base, nb, s0, s1);
    const float4* am = (const float4*)(g_amps + (size_t)node * K_);
    float4 a0 = am[0], a1 = am[1];
    float4* o = (float4*)(out + (size_t)node * K_);
    o[0] = make_float4(s0.x * a0.x, s0.y * a0.y, s0.z * a0.z, s0.w * a0.w);
    o[1] = make_float4(s1.x * a1.x, s1.y * a1.y, s1.z * a1.z, s1.w * a1.w);
}

__global__ void spmm_step1(const int* __restrict__ neighbors) { spmm_body(g_amps, g_bufA, neighbors); }
__global__ void spmm_step2(const int* __restrict__ neighbors) { spmm_body(g_bufA, g_bufB, neighbors); }

__global__ void spmm_final(const int* __restrict__ neighbors) {
    int node = blockIdx.x * blockDim.x + threadIdx.x;
    int b = node >> 13;
    const int4* nb = (const int4*)(neighbors + (size_t)node * DEG_);
    const float4* base = (const float4*)(g_bufB + (size_t)b * N_ * K_);
    float4 s0, s1;
    gather16(base, nb, s0, s1);
    float absum = fabsf(s0.x) + fabsf(s0.y) + fabsf(s0.z) + fabsf(s0.w)
                + fabsf(s1.x) + fabsf(s1.y) + fabsf(s1.z) + fabsf(s1.w);
    float ss = s0.x * s0.x + s0.y * s0.y + s0.z * s0.z + s0.w * s0.w
             + s1.x * s1.x + s1.y * s1.y + s1.z * s1.z + s1.w * s1.w;
    g_absum[node] = absum;

    __shared__ float red[256];
    int t = threadIdx.x;
    red[t] = ss;
    __syncthreads();
#pragma unroll
    for (int s = 128; s > 0; s >>= 1) {
        if (t < s) red[t] += red[t + s];
        __syncthreads();
    }
    if (t == 0) g_part[blockIdx.x] = red[0];
}

__global__ void finalize(float* __restrict__ out) {
    __shared__ float ssum;
    int node = blockIdx.x * blockDim.x + threadIdx.x;
    int b = node >> 13;
    if (threadIdx.x < 32) {
        float s = g_part[b * 32 + threadIdx.x];
#pragma unroll
        for (int off = 16; off > 0; off >>= 1)
            s += __shfl_xor_sync(0xffffffffu, s, off);
        if (threadIdx.x == 0) ssum = s;
    }
    __syncthreads();
    float ss = ssum;
    float scale = (ss > 0.f) ? rsqrtf(ss) : 1.f;
    out[node] = g_absum[node] * scale;
}

// ---------------- launch ----------------
extern "C" void kernel_launch(void* const* d_in, const int* in_sizes, int n_in,
                              void* d_out, int out_size) {
    const float* q_embs    = (const float*)d_in[0];
    const float* emb       = (const float*)d_in[1];
    const int*   neighbors = (const int*)d_in[2];
    const int*   labels    = (const int*)d_in[3];
    const float* W1        = (const float*)d_in[4];
    const float* b1        = (const float*)d_in[5];
    const float* W2        = (const float*)d_in[6];
    const float* b2        = (const float*)d_in[7];
    const float* P1        = (const float*)d_in[8];
    const float* pb1       = (const float*)d_in[9];
    const float* P2        = (const float*)d_in[10];
    const float* pb2       = (const float*)d_in[11];
    float* out = (float*)d_out;

    cudaFuncSetAttribute(gemm_tc, cudaFuncAttributeMaxDynamicSharedMemorySize, SM_TOTAL);

    prep_wt<<<(WCOLS * D_) / 256, 256>>>(W1, P1);
    prep_qc<<<B_, 256>>>(q_embs, W1, b1, P1, pb1);
    prep_small<<<1, 1024>>>(W2, b2, P2, pb2);
    gemm_tc<<<(NODES / MTILE) * 2, 256, SM_TOTAL>>>(emb, labels);
    finalize_amps<<<NODES / 256, 256>>>();
    spmm_step1<<<NODES / 256, 256>>>(neighbors);
    spmm_step2<<<NODES / 256, 256>>>(neighbors);
    spmm_final<<<NODES / 256, 256>>>(neighbors);
    finalize<<<NODES / 256, 256>>>(out);
}

// round 15
// speedup vs baseline: 1.3936x; 1.0736x over previous
#include <cuda_runtime.h>
#include <cuda_fp16.h>
#include <math.h>
#include <stdint.h>

#define B_    16
#define N_    8192
#define D_    384
#define DEG_  16
#define K_    8
#define H_    128
#define NODES (B_ * N_)
#define WCOLS 256
#define MTILE 64          // rows per CTA
#define NTILE 128         // cols per CTA (one half)
#define KCH   32
#define NCH   (D_ / KCH)  // 12
#define STSC  (1.0f / 256.0f)   // per-step state scale (cancels in final norm)

// ---- smem layout (bytes) ----
#define SM_QC     0
#define SM_W2     512
#define SM_P2     4608
#define SM_B2     5120
#define SM_PB2    5152
#define SM_A      5632       // 3 bufs x 4KB
#define SM_B      17920      // 3 bufs x 8KB
#define SM_TOTAL  42496
#define SM_EPART  5632

__device__ float g_qc[B_ * WCOLS];
__device__ __half g_WT[WCOLS * D_];
__device__ float g_W2[H_ * K_];
__device__ float g_P2[H_];
__device__ float g_b2[K_];
__device__ float g_pb2[1];
__device__ float g_s[NODES * K_];
__device__ float g_factor[NODES];
__device__ float g_amps[NODES * K_];    // fp32, own-node multiplier (coalesced)
__device__ uint4 g_ampsh[NODES];        // fp16x8, gather operand
__device__ uint4 g_buf1h[NODES];        // fp16 state buffers
__device__ uint4 g_buf2h[NODES];
__device__ float g_absum[NODES];
__device__ float g_part[512];

// ---------------- helpers ----------------
__device__ __forceinline__ uint32_t smem_u32(const void* p) {
    uint32_t a;
    asm("{ .reg .u64 t; cvta.to.shared.u64 t, %1; cvt.u32.u64 %0, t; }" : "=r"(a) : "l"(p));
    return a;
}
__device__ __forceinline__ uint32_t pk2h(__half a, __half b) {
    __half2 t(a, b);
    return *reinterpret_cast<uint32_t*>(&t);
}
__device__ __forceinline__ uint32_t off64(int r, int g) {
    uint32_t line = (uint32_t)(r >> 1);
    uint32_t col = (uint32_t)(((r & 1) << 6) | (g << 4));
    return line * 128 + (col ^ ((line & 7) << 4));
}
__device__ __forceinline__ void cp16(uint32_t dst, const void* src) {
    asm volatile("cp.async.cg.shared.global [%0], [%1], 16;" :: "r"(dst), "l"(src) : "memory");
}
__device__ __forceinline__ void cp_commit() {
    asm volatile("cp.async.commit_group;" ::: "memory");
}
__device__ __forceinline__ void mma_f16(float* d, const uint32_t* a, const uint32_t* b) {
    asm volatile(
        "mma.sync.aligned.m16n8k16.row.col.f32.f16.f16.f32 "
        "{%0,%1,%2,%3}, {%4,%5,%6,%7}, {%8,%9}, {%0,%1,%2,%3};"
        : "+f"(d[0]), "+f"(d[1]), "+f"(d[2]), "+f"(d[3])
        : "r"(a[0]), "r"(a[1]), "r"(a[2]), "r"(a[3]), "r"(b[0]), "r"(b[1]));
}
__device__ __forceinline__ void ldm_x4(uint32_t& r0, uint32_t& r1, uint32_t& r2, uint32_t& r3,
                                       uint32_t addr) {
    asm volatile("ldmatrix.sync.aligned.m8n8.x4.shared.b16 {%0,%1,%2,%3}, [%4];"
                 : "=r"(r0), "=r"(r1), "=r"(r2), "=r"(r3) : "r"(addr));
}
__device__ __forceinline__ void acc_h(uint4 v, float4& s0, float4& s1) {
    const __half2* h = reinterpret_cast<const __half2*>(&v);
    float2 f;
    f = __half22float2(h[0]); s0.x += f.x; s0.y += f.y;
    f = __half22float2(h[1]); s0.z += f.x; s0.w += f.y;
    f = __half22float2(h[2]); s1.x += f.x; s1.y += f.y;
    f = __half22float2(h[3]); s1.z += f.x; s1.w += f.y;
}
__device__ __forceinline__ uint4 pack_h(float4 a, float4 b) {
    uint4 r;
    __half2 h;
    h = __floats2half2_rn(a.x, a.y); r.x = *reinterpret_cast<uint32_t*>(&h);
    h = __floats2half2_rn(a.z, a.w); r.y = *reinterpret_cast<uint32_t*>(&h);
    h = __floats2half2_rn(b.x, b.y); r.z = *reinterpret_cast<uint32_t*>(&h);
    h = __floats2half2_rn(b.z, b.w); r.w = *reinterpret_cast<uint32_t*>(&h);
    return r;
}

// ---------------- prep (merged): blocks 0-383 wt, 384-399 qc, 400 small ----------------
__global__ void prep_all(const float* __restrict__ q,
                         const float* __restrict__ W1, const float* __restrict__ b1,
                         const float* __restrict__ W2, const float* __restrict__ b2,
                         const float* __restrict__ P1, const float* __restrict__ pb1,
                         const float* __restrict__ P2, const float* __restrict__ pb2) {
    __shared__ float qs[D_];
    int bx = blockIdx.x;
    int j = threadIdx.x;
    if (bx < 384) {
        int i = bx * 256 + j;               // 98304 = 256*384 elements
        int n = i / D_;
        int kd = i - n * D_;
        float v = (n < H_) ? W1[kd * H_ + n] : P1[kd * H_ + (n - H_)];
        g_WT[i] = __float2half_rn(v);
    } else if (bx < 400) {
        int b = bx - 384;
        for (int d = j; d < D_; d += 256) qs[d] = q[b * D_ + d];
        __syncthreads();
        float s;
        const float* w;
        if (j < H_) { s = b1[j];       w = W1 + (size_t)D_ * H_ + j; }
        else        { s = pb1[j - H_]; w = P1 + (size_t)D_ * H_ + (j - H_); }
#pragma unroll 4
        for (int d = 0; d < D_; d++) s = fmaf(qs[d], w[(size_t)d * H_], s);
        g_qc[b * WCOLS + j] = s;
    } else {
        for (int i = j; i < H_ * K_; i += 256) g_W2[i] = W2[i];
        if (j < H_) g_P2[j] = P2[j];
        if (j < K_) g_b2[j] = b2[j];
        if (j == 0) g_pb2[0] = pb2[0];
    }
}

// ---------------- GEMM (frozen from R13): 64x128/CTA, 8 warps, 3 CTAs/SM ----------------
__global__ __launch_bounds__(256, 3)
void gemm_tc(const float* __restrict__ emb, const int* __restrict__ labels) {
    extern __shared__ char smem[];
    const uint32_t sb = smem_u32(smem);
    const int tid = threadIdx.x;
    const int wid = tid >> 5;
    const int lane = tid & 31;
    const int half = blockIdx.x & 1;
    const int row0 = (blockIdx.x >> 1) * MTILE;
    const int b = row0 >> 13;
    const int nbase = half * NTILE;

    if (tid < NTILE) ((float*)(smem + SM_QC))[tid] = g_qc[b * WCOLS + nbase + tid];
#pragma unroll
    for (int j = 0; j < 4; j++)
        ((float*)(smem + SM_W2))[tid * 4 + j] = g_W2[tid * 4 + j];
    if (tid < H_) ((float*)(smem + SM_P2))[tid] = g_P2[tid];
    if (tid < K_) ((float*)(smem + SM_B2))[tid] = g_b2[tid];
    if (tid == 0) *((float*)(smem + SM_PB2)) = g_pb2[0];

    const __half* WBase = g_WT + (size_t)nbase * D_;
    const int bn0 = (tid * 2) >> 2, bg0 = (tid * 2) & 3;
    const int bn1 = (tid * 2 + 1) >> 2, bg1 = (tid * 2 + 1) & 3;
    const uint32_t bo0 = off64(bn0, bg0);
    const uint32_t bo1 = off64(bn1, bg1);
    const char* src0 = (const char*)(WBase + (size_t)bn0 * D_) + bg0 * 16;
    const char* src1 = (const char*)(WBase + (size_t)bn1 * D_) + bg1 * 16;

    auto issueB = [&](int c, int buf) {
        uint32_t bb = sb + SM_B + buf * 8192;
        size_t koff = (size_t)c * KCH * 2;
        cp16(bb + bo0, src0 + koff);
        cp16(bb + bo1, src1 + koff);
        cp_commit();
    };

    const int ar = tid >> 2;
    const int aq = tid & 3;
    const float* abase = emb + (size_t)(row0 + ar) * D_ + aq * 8;
    const uint32_t aSts = off64(ar, aq);

    auto stsA = [&](const float4& v0, const float4& v1, int buf) {
        uint32_t ab = sb + SM_A + buf * 4096;
        uint32_t p0 = pk2h(__float2half_rn(v0.x), __float2half_rn(v0.y));
        uint32_t p1 = pk2h(__float2half_rn(v0.z), __float2half_rn(v0.w));
        uint32_t p2 = pk2h(__float2half_rn(v1.x), __float2half_rn(v1.y));
        uint32_t p3 = pk2h(__float2half_rn(v1.z), __float2half_rn(v1.w));
        asm volatile("st.shared.v4.b32 [%0], {%1,%2,%3,%4};" :: "r"(ab + aSts),
                     "r"(p0), "r"(p1), "r"(p2), "r"(p3) : "memory");
    };

    issueB(0, 0);
    issueB(1, 1);
    float4 pv0 = *(const float4*)(abase + 0);
    float4 pv1 = *(const float4*)(abase + 4);
    stsA(pv0, pv1, 0);
    pv0 = *(const float4*)(abase + KCH + 0);
    pv1 = *(const float4*)(abase + KCH + 4);

    float acc[2][4][4];
#pragma unroll
    for (int i = 0; i < 2; i++)
#pragma unroll
        for (int j = 0; j < 4; j++)
#pragma unroll
            for (int k = 0; k < 4; k++) acc[i][j][k] = 0.f;

    const int wm = wid >> 2;
    const int wn = wid & 3;
    const int m0 = wm * 32;
    const int n0w = wn * 32;
    const int g4 = lane >> 2;
    const int t4 = lane & 3;

    const int lr = lane & 7;
    const int sel = lane >> 3;
    uint32_t aOff[2][2], bOff[2][2];
#pragma unroll
    for (int mf = 0; mf < 2; mf++) {
        int rA = m0 + mf * 16 + lr + ((sel & 1) ? 8 : 0);
#pragma unroll
        for (int ks = 0; ks < 2; ks++)
            aOff[mf][ks] = off64(rA, ks * 2 + ((sel >> 1) & 1));
    }
#pragma unroll
    for (int nfp = 0; nfp < 2; nfp++) {
        int rB = n0w + nfp * 16 + ((sel >> 1) ? 8 : 0) + lr;
#pragma unroll
        for (int ks = 0; ks < 2; ks++)
            bOff[nfp][ks] = off64(rB, ks * 2 + (sel & 1));
    }

    int bufc = 0;
    for (int c = 0; c < NCH; c++) {
        if (c == NCH - 1) asm volatile("cp.async.wait_group 0;" ::: "memory");
        else              asm volatile("cp.async.wait_group 1;" ::: "memory");
        __syncthreads();

        {
            int buf2 = bufc + 2; if (buf2 >= 3) buf2 -= 3;
            int buf1 = bufc + 1; if (buf1 >= 3) buf1 -= 3;
            if (c + 2 < NCH) issueB(c + 2, buf2);
            if (c + 1 < NCH) stsA(pv0, pv1, buf1);
            if (c + 2 < NCH) {
                const float* nb = abase + (c + 2) * KCH;
                pv0 = *(const float4*)(nb + 0);
                pv1 = *(const float4*)(nb + 4);
            }
        }

        const uint32_t AB = sb + SM_A + bufc * 4096;
        const uint32_t BB = sb + SM_B + bufc * 8192;

#pragma unroll
        for (int ks = 0; ks < 2; ks++) {
            uint32_t ah[2][4], bh[4][2];
#pragma unroll
            for (int nfp = 0; nfp < 2; nfp++)
                ldm_x4(bh[nfp * 2][0], bh[nfp * 2][1], bh[nfp * 2 + 1][0], bh[nfp * 2 + 1][1],
                       BB + bOff[nfp][ks]);
#pragma unroll
            for (int mf = 0; mf < 2; mf++)
                ldm_x4(ah[mf][0], ah[mf][1], ah[mf][2], ah[mf][3], AB + aOff[mf][ks]);
#pragma unroll
            for (int mf = 0; mf < 2; mf++)
#pragma unroll
                for (int nf = 0; nf < 4; nf++)
                    mma_f16(acc[mf][nf], ah[mf], bh[nf]);
        }
        if (++bufc == 3) bufc = 0;
    }
    __syncthreads();

    const float* qcs = (const float*)(smem + SM_QC);
    const float* W2s = (const float*)(smem + SM_W2);
    const float* P2s = (const float*)(smem + SM_P2);
    float* epart = (float*)(smem + SM_EPART);

    if (half == 0) {
#pragma unroll
        for (int mf = 0; mf < 2; mf++) {
#pragma unroll
            for (int rg = 0; rg < 2; rg++) {
                int rowl = m0 + mf * 16 + g4 + rg * 8;
                float p[8] = {0.f, 0.f, 0.f, 0.f, 0.f, 0.f, 0.f, 0.f};
#pragma unroll
                for (int nf = 0; nf < 4; nf++) {
#pragma unroll
                    for (int cp = 0; cp < 2; cp++) {
                        int lc = n0w + nf * 8 + t4 * 2 + cp;
                        float hv = fmaxf(acc[mf][nf][rg * 2 + cp] + qcs[lc], 0.f);
                        const float* w = W2s + lc * 8;
#pragma unroll
                        for (int k = 0; k < 8; k++) p[k] = fmaf(hv, w[k], p[k]);
                    }
                }
#pragma unroll
                for (int k = 0; k < 8; k++) {
                    p[k] += __shfl_xor_sync(0xffffffffu, p[k], 1);
                    p[k] += __shfl_xor_sync(0xffffffffu, p[k], 2);
                }
                if (t4 == 0) {
#pragma unroll
                    for (int k = 0; k < 8; k++)
                        epart[((size_t)wn * 64 + rowl) * 8 + k] = p[k];
                }
            }
        }
        __syncthreads();
        const float* b2s = (const float*)(smem + SM_B2);
        for (int t = tid; t < 64 * 8; t += 256) {
            int r = t >> 3, k = t & 7;
            float s = epart[(0 * 64 + r) * 8 + k] + epart[(1 * 64 + r) * 8 + k]
                    + epart[(2 * 64 + r) * 8 + k] + epart[(3 * 64 + r) * 8 + k];
            g_s[(size_t)(row0 + r) * K_ + k] = s + b2s[k];
        }
    } else {
#pragma unroll
        for (int mf = 0; mf < 2; mf++) {
#pragma unroll
            for (int rg = 0; rg < 2; rg++) {
                int rowl = m0 + mf * 16 + g4 + rg * 8;
                float p8 = 0.f;
#pragma unroll
                for (int nf = 0; nf < 4; nf++) {
#pragma unroll
                    for (int cp = 0; cp < 2; cp++) {
                        int lc = n0w + nf * 8 + t4 * 2 + cp;
                        float hv = fmaxf(acc[mf][nf][rg * 2 + cp] + qcs[lc], 0.f);
                        p8 = fmaf(hv, P2s[lc], p8);
                    }
                }
                p8 += __shfl_xor_sync(0xffffffffu, p8, 1);
                p8 += __shfl_xor_sync(0xffffffffu, p8, 2);
                if (t4 == 0) epart[(size_t)wn * 64 + rowl] = p8;
            }
        }
        __syncthreads();
        if (tid < 64) {
            float logit = epart[0 * 64 + tid] + epart[1 * 64 + tid]
                        + epart[2 * 64 + tid] + epart[3 * 64 + tid]
                        + *((const float*)(smem + SM_PB2));
            int row = row0 + tid;
            float factor = 1.f + 1.f / (1.f + expf(-logit)) + (float)labels[row];
            g_factor[row] = factor;
        }
    }
}

// ---------------- amps = s * factor (fp32 + fp16 copies) ----------------
__global__ void finalize_amps() {
    int node = blockIdx.x * blockDim.x + threadIdx.x;
    float f = g_factor[node];
    const float4* s = (const float4*)(g_s + (size_t)node * K_);
    float4 s0 = s[0], s1 = s[1];
    float4 a0 = make_float4(s0.x * f, s0.y * f, s0.z * f, s0.w * f);
    float4 a1 = make_float4(s1.x * f, s1.y * f, s1.z * f, s1.w * f);
    float4* o = (float4*)(g_amps + (size_t)node * K_);
    o[0] = a0;
    o[1] = a1;
    g_ampsh[node] = pack_h(a0, a1);
}

// ---------------- fp16 diffusion ----------------
__device__ __forceinline__ void gather16h(const uint4* __restrict__ base,
                                          const int4* __restrict__ nb,
                                          float4& s0, float4& s1) {
    s0 = make_float4(0.f, 0.f, 0.f, 0.f);
    s1 = make_float4(0.f, 0.f, 0.f, 0.f);
#pragma unroll
    for (int j = 0; j < 4; j++) {
        int4 id = nb[j];
        acc_h(base[id.x], s0, s1);
        acc_h(base[id.y], s0, s1);
        acc_h(base[id.z], s0, s1);
        acc_h(base[id.w], s0, s1);
    }
}

__device__ __forceinline__ void spmm_body_h(const uint4* __restrict__ in,
                                            uint4* __restrict__ out,
                                            const int* __restrict__ neighbors) {
    int node = blockIdx.x * blockDim.x + threadIdx.x;
    int b = node >> 13;
    const int4* nb = (const int4*)(neighbors + (size_t)node * DEG_);
    const uint4* base = in + (size_t)b * N_;
    float4 s0, s1;
    gather16h(base, nb, s0, s1);
    const float4* am = (const float4*)(g_amps + (size_t)node * K_);
    float4 a0 = am[0], a1 = am[1];
    float4 o0 = make_float4(s0.x * a0.x * STSC, s0.y * a0.y * STSC,
                            s0.z * a0.z * STSC, s0.w * a0.w * STSC);
    float4 o1 = make_float4(s1.x * a1.x * STSC, s1.y * a1.y * STSC,
                            s1.z * a1.z * STSC, s1.w * a1.w * STSC);
    out[node] = pack_h(o0, o1);
}

__global__ void spmm_step1(const int* __restrict__ neighbors) { spmm_body_h(g_ampsh, g_buf1h, neighbors); }
__global__ void spmm_step2(const int* __restrict__ neighbors) { spmm_body_h(g_buf1h, g_buf2h, neighbors); }

__global__ void spmm_final(const int* __restrict__ neighbors) {
    int node = blockIdx.x * blockDim.x + threadIdx.x;
    int b = node >> 13;
    const int4* nb = (const int4*)(neighbors + (size_t)node * DEG_);
    const uint4* base = g_buf2h + (size_t)b * N_;
    float4 s0, s1;
    gather16h(base, nb, s0, s1);
    float absum = fabsf(s0.x) + fabsf(s0.y) + fabsf(s0.z) + fabsf(s0.w)
                + fabsf(s1.x) + fabsf(s1.y) + fabsf(s1.z) + fabsf(s1.w);
    float ss = s0.x * s0.x + s0.y * s0.y + s0.z * s0.z + s0.w * s0.w
             + s1.x * s1.x + s1.y * s1.y + s1.z * s1.z + s1.w * s1.w;
    g_absum[node] = absum;

    __shared__ float red[256];
    int t = threadIdx.x;
    red[t] = ss;
    __syncthreads();
#pragma unroll
    for (int s = 128; s > 0; s >>= 1) {
        if (t < s) red[t] += red[t + s];
        __syncthreads();
    }
    if (t == 0) g_part[blockIdx.x] = red[0];
}

__global__ void finalize(float* __restrict__ out) {
    __shared__ float ssum;
    int node = blockIdx.x * blockDim.x + threadIdx.x;
    int b = node >> 13;
    if (threadIdx.x < 32) {
        float s = g_part[b * 32 + threadIdx.x];
#pragma unroll
        for (int off = 16; off > 0; off >>= 1)
            s += __shfl_xor_sync(0xffffffffu, s, off);
        if (threadIdx.x == 0) ssum = s;
    }
    __syncthreads();
    float ss = ssum;
    float scale = (ss > 0.f) ? rsqrtf(ss) : 1.f;
    out[node] = g_absum[node] * scale;
}

// ---------------- launch ----------------
extern "C" void kernel_launch(void* const* d_in, const int* in_sizes, int n_in,
                              void* d_out, int out_size) {
    const float* q_embs    = (const float*)d_in[0];
    const float* emb       = (const float*)d_in[1];
    const int*   neighbors = (const int*)d_in[2];
    const int*   labels    = (const int*)d_in[3];
    const float* W1        = (const float*)d_in[4];
    const float* b1        = (const float*)d_in[5];
    const float* W2        = (const float*)d_in[6];
    const float* b2        = (const float*)d_in[7];
    const float* P1        = (const float*)d_in[8];
    const float* pb1       = (const float*)d_in[9];
    const float* P2        = (const float*)d_in[10];
    const float* pb2       = (const float*)d_in[11];
    float* out = (float*)d_out;

    cudaFuncSetAttribute(gemm_tc, cudaFuncAttributeMaxDynamicSharedMemorySize, SM_TOTAL);

    prep_all<<<401, 256>>>(q_embs, W1, b1, W2, b2, P1, pb1, P2, pb2);
    gemm_tc<<<(NODES / MTILE) * 2, 256, SM_TOTAL>>>(emb, labels);
    finalize_amps<<<NODES / 256, 256>>>();
    spmm_step1<<<NODES / 256, 256>>>(neighbors);
    spmm_step2<<<NODES / 256, 256>>>(neighbors);
    spmm_final<<<NODES / 256, 256>>>(neighbors);
    finalize<<<NODES / 256, 256>>>(out);
}

// round 17
// speedup vs baseline: 1.4221x; 1.0204x over previous
#include <cuda_runtime.h>
#include <cuda_fp16.h>
#include <math.h>
#include <stdint.h>

#define B_    16
#define N_    8192
#define D_    384
#define DEG_  16
#define K_    8
#define H_    128
#define NODES (B_ * N_)
#define WCOLS 256
#define MTILE 64
#define NTILE 128
#define KCH   32
#define NCH   (D_ / KCH)
#define STSC  (1.0f / 256.0f)
#define WCTAS 512               // fused walk kernel CTAs (1 thread per node)

// ---- smem layout (bytes) ----
#define SM_QC     0
#define SM_W2     512
#define SM_P2     4608
#define SM_B2     5120
#define SM_PB2    5152
#define SM_A      5632
#define SM_B      17920
#define SM_TOTAL  42496
#define SM_EPART  5632

__device__ float g_qc[B_ * WCOLS];
__device__ __half g_WT[WCOLS * D_];
__device__ float g_W2[H_ * K_];
__device__ float g_P2[H_];
__device__ float g_b2[K_];
__device__ float g_pb2[1];
__device__ float g_s[NODES * K_];
__device__ float g_factor[NODES];
__device__ float g_amps[NODES * K_];
__device__ uint4 g_ampsh[NODES];
__device__ uint4 g_buf1h[NODES];
__device__ uint4 g_buf2h[NODES];
__device__ float g_part[WCTAS];
__device__ volatile unsigned g_barcnt[4];

// ---------------- helpers ----------------
__device__ __forceinline__ uint32_t smem_u32(const void* p) {
    uint32_t a;
    asm("{ .reg .u64 t; cvta.to.shared.u64 t, %1; cvt.u32.u64 %0, t; }" : "=r"(a) : "l"(p));
    return a;
}
__device__ __forceinline__ uint32_t pk2h(__half a, __half b) {
    __half2 t(a, b);
    return *reinterpret_cast<uint32_t*>(&t);
}
__device__ __forceinline__ uint32_t off64(int r, int g) {
    uint32_t line = (uint32_t)(r >> 1);
    uint32_t col = (uint32_t)(((r & 1) << 6) | (g << 4));
    return line * 128 + (col ^ ((line & 7) << 4));
}
__device__ __forceinline__ void cp16(uint32_t dst, const void* src) {
    asm volatile("cp.async.cg.shared.global [%0], [%1], 16;" :: "r"(dst), "l"(src) : "memory");
}
__device__ __forceinline__ void cp_commit() {
    asm volatile("cp.async.commit_group;" ::: "memory");
}
__device__ __forceinline__ void mma_f16(float* d, const uint32_t* a, const uint32_t* b) {
    asm volatile(
        "mma.sync.aligned.m16n8k16.row.col.f32.f16.f16.f32 "
        "{%0,%1,%2,%3}, {%4,%5,%6,%7}, {%8,%9}, {%0,%1,%2,%3};"
        : "+f"(d[0]), "+f"(d[1]), "+f"(d[2]), "+f"(d[3])
        : "r"(a[0]), "r"(a[1]), "r"(a[2]), "r"(a[3]), "r"(b[0]), "r"(b[1]));
}
__device__ __forceinline__ void ldm_x4(uint32_t& r0, uint32_t& r1, uint32_t& r2, uint32_t& r3,
                                       uint32_t addr) {
    asm volatile("ldmatrix.sync.aligned.m8n8.x4.shared.b16 {%0,%1,%2,%3}, [%4];"
                 : "=r"(r0), "=r"(r1), "=r"(r2), "=r"(r3) : "r"(addr));
}
__device__ __forceinline__ void acc_h(uint4 v, float4& s0, float4& s1) {
    const __half2* h = reinterpret_cast<const __half2*>(&v);
    float2 f;
    f = __half22float2(h[0]); s0.x += f.x; s0.y += f.y;
    f = __half22float2(h[1]); s0.z += f.x; s0.w += f.y;
    f = __half22float2(h[2]); s1.x += f.x; s1.y += f.y;
    f = __half22float2(h[3]); s1.z += f.x; s1.w += f.y;
}
__device__ __forceinline__ uint4 pack_h(float4 a, float4 b) {
    uint4 r;
    __half2 h;
    h = __floats2half2_rn(a.x, a.y); r.x = *reinterpret_cast<uint32_t*>(&h);
    h = __floats2half2_rn(a.z, a.w); r.y = *reinterpret_cast<uint32_t*>(&h);
    h = __floats2half2_rn(b.x, b.y); r.z = *reinterpret_cast<uint32_t*>(&h);
    h = __floats2half2_rn(b.z, b.w); r.w = *reinterpret_cast<uint32_t*>(&h);
    return r;
}
__device__ __forceinline__ void gridbar(int i, unsigned target) {
    __syncthreads();
    if (threadIdx.x == 0) {
        __threadfence();
        atomicAdd((unsigned*)&g_barcnt[i], 1u);
        while (g_barcnt[i] < target) { }
        __threadfence();
    }
    __syncthreads();
}

// ---------------- prep (merged): 0-95 wt transpose, 96-111 qc, 112 small+reset ----------------
__global__ void prep_all(const float* __restrict__ q,
                         const float* __restrict__ W1, const float* __restrict__ b1,
                         const float* __restrict__ W2, const float* __restrict__ b2,
                         const float* __restrict__ P1, const float* __restrict__ pb1,
                         const float* __restrict__ P2, const float* __restrict__ pb2) {
    __shared__ float ts[32][33];
    __shared__ float qs[D_];
    int bx = blockIdx.x;
    int j = threadIdx.x;
    if (bx < 96) {
        // transpose tile: n-block tn = bx & 7 (32 n's), kd-block tk = bx >> 3 (32 kd's)
        int tn = (bx & 7) * 32;
        int tk = (bx >> 3) * 32;
        int tx = j & 31, ty = j >> 5;            // ty 0..7
        const float* src = (tn < H_) ? (W1 + tn) : (P1 + (tn - H_));
#pragma unroll
        for (int r = 0; r < 4; r++) {
            int kd = ty * 4 + r;
            ts[kd][tx] = src[(size_t)(tk + kd) * H_ + tx];
        }
        __syncthreads();
#pragma unroll
        for (int r = 0; r < 4; r++) {
            int nl = ty * 4 + r;
            g_WT[(size_t)(tn + nl) * D_ + tk + tx] = __float2half_rn(ts[tx][nl]);
        }
    } else if (bx < 112) {
        int b = bx - 96;
        for (int d = j; d < D_; d += 256) qs[d] = q[b * D_ + d];
        __syncthreads();
        float s;
        const float* w;
        if (j < H_) { s = b1[j];       w = W1 + (size_t)D_ * H_ + j; }
        else        { s = pb1[j - H_]; w = P1 + (size_t)D_ * H_ + (j - H_); }
#pragma unroll 4
        for (int d = 0; d < D_; d++) s = fmaf(qs[d], w[(size_t)d * H_], s);
        g_qc[b * WCOLS + j] = s;
    } else {
        for (int i = j; i < H_ * K_; i += 256) g_W2[i] = W2[i];
        if (j < H_) g_P2[j] = P2[j];
        if (j < K_) g_b2[j] = b2[j];
        if (j == 0) g_pb2[0] = pb2[0];
        if (j < 4) g_barcnt[j] = 0;          // reset fused-walk barriers each replay
    }
}

// ---------------- GEMM (frozen from R13): 64x128/CTA, 8 warps, 3 CTAs/SM ----------------
__global__ __launch_bounds__(256, 3)
void gemm_tc(const float* __restrict__ emb, const int* __restrict__ labels) {
    extern __shared__ char smem[];
    const uint32_t sb = smem_u32(smem);
    const int tid = threadIdx.x;
    const int wid = tid >> 5;
    const int lane = tid & 31;
    const int half = blockIdx.x & 1;
    const int row0 = (blockIdx.x >> 1) * MTILE;
    const int b = row0 >> 13;
    const int nbase = half * NTILE;

    if (tid < NTILE) ((float*)(smem + SM_QC))[tid] = g_qc[b * WCOLS + nbase + tid];
#pragma unroll
    for (int j = 0; j < 4; j++)
        ((float*)(smem + SM_W2))[tid * 4 + j] = g_W2[tid * 4 + j];
    if (tid < H_) ((float*)(smem + SM_P2))[tid] = g_P2[tid];
    if (tid < K_) ((float*)(smem + SM_B2))[tid] = g_b2[tid];
    if (tid == 0) *((float*)(smem + SM_PB2)) = g_pb2[0];

    const __half* WBase = g_WT + (size_t)nbase * D_;
    const int bn0 = (tid * 2) >> 2, bg0 = (tid * 2) & 3;
    const int bn1 = (tid * 2 + 1) >> 2, bg1 = (tid * 2 + 1) & 3;
    const uint32_t bo0 = off64(bn0, bg0);
    const uint32_t bo1 = off64(bn1, bg1);
    const char* src0 = (const char*)(WBase + (size_t)bn0 * D_) + bg0 * 16;
    const char* src1 = (const char*)(WBase + (size_t)bn1 * D_) + bg1 * 16;

    auto issueB = [&](int c, int buf) {
        uint32_t bb = sb + SM_B + buf * 8192;
        size_t koff = (size_t)c * KCH * 2;
        cp16(bb + bo0, src0 + koff);
        cp16(bb + bo1, src1 + koff);
        cp_commit();
    };

    const int ar = tid >> 2;
    const int aq = tid & 3;
    const float* abase = emb + (size_t)(row0 + ar) * D_ + aq * 8;
    const uint32_t aSts = off64(ar, aq);

    auto stsA = [&](const float4& v0, const float4& v1, int buf) {
        uint32_t ab = sb + SM_A + buf * 4096;
        uint32_t p0 = pk2h(__float2half_rn(v0.x), __float2half_rn(v0.y));
        uint32_t p1 = pk2h(__float2half_rn(v0.z), __float2half_rn(v0.w));
        uint32_t p2 = pk2h(__float2half_rn(v1.x), __float2half_rn(v1.y));
        uint32_t p3 = pk2h(__float2half_rn(v1.z), __float2half_rn(v1.w));
        asm volatile("st.shared.v4.b32 [%0], {%1,%2,%3,%4};" :: "r"(ab + aSts),
                     "r"(p0), "r"(p1), "r"(p2), "r"(p3) : "memory");
    };

    issueB(0, 0);
    issueB(1, 1);
    float4 pv0 = *(const float4*)(abase + 0);
    float4 pv1 = *(const float4*)(abase + 4);
    stsA(pv0, pv1, 0);
    pv0 = *(const float4*)(abase + KCH + 0);
    pv1 = *(const float4*)(abase + KCH + 4);

    float acc[2][4][4];
#pragma unroll
    for (int i = 0; i < 2; i++)
#pragma unroll
        for (int j = 0; j < 4; j++)
#pragma unroll
            for (int k = 0; k < 4; k++) acc[i][j][k] = 0.f;

    const int wm = wid >> 2;
    const int wn = wid & 3;
    const int m0 = wm * 32;
    const int n0w = wn * 32;
    const int g4 = lane >> 2;
    const int t4 = lane & 3;

    const int lr = lane & 7;
    const int sel = lane >> 3;
    uint32_t aOff[2][2], bOff[2][2];
#pragma unroll
    for (int mf = 0; mf < 2; mf++) {
        int rA = m0 + mf * 16 + lr + ((sel & 1) ? 8 : 0);
#pragma unroll
        for (int ks = 0; ks < 2; ks++)
            aOff[mf][ks] = off64(rA, ks * 2 + ((sel >> 1) & 1));
    }
#pragma unroll
    for (int nfp = 0; nfp < 2; nfp++) {
        int rB = n0w + nfp * 16 + ((sel >> 1) ? 8 : 0) + lr;
#pragma unroll
        for (int ks = 0; ks < 2; ks++)
            bOff[nfp][ks] = off64(rB, ks * 2 + (sel & 1));
    }

    int bufc = 0;
    for (int c = 0; c < NCH; c++) {
        if (c == NCH - 1) asm volatile("cp.async.wait_group 0;" ::: "memory");
        else              asm volatile("cp.async.wait_group 1;" ::: "memory");
        __syncthreads();

        {
            int buf2 = bufc + 2; if (buf2 >= 3) buf2 -= 3;
            int buf1 = bufc + 1; if (buf1 >= 3) buf1 -= 3;
            if (c + 2 < NCH) issueB(c + 2, buf2);
            if (c + 1 < NCH) stsA(pv0, pv1, buf1);
            if (c + 2 < NCH) {
                const float* nb = abase + (c + 2) * KCH;
                pv0 = *(const float4*)(nb + 0);
                pv1 = *(const float4*)(nb + 4);
            }
        }

        const uint32_t AB = sb + SM_A + bufc * 4096;
        const uint32_t BB = sb + SM_B + bufc * 8192;

#pragma unroll
        for (int ks = 0; ks < 2; ks++) {
            uint32_t ah[2][4], bh[4][2];
#pragma unroll
            for (int nfp = 0; nfp < 2; nfp++)
                ldm_x4(bh[nfp * 2][0], bh[nfp * 2][1], bh[nfp * 2 + 1][0], bh[nfp * 2 + 1][1],
                       BB + bOff[nfp][ks]);
#pragma unroll
            for (int mf = 0; mf < 2; mf++)
                ldm_x4(ah[mf][0], ah[mf][1], ah[mf][2], ah[mf][3], AB + aOff[mf][ks]);
#pragma unroll
            for (int mf = 0; mf < 2; mf++)
#pragma unroll
                for (int nf = 0; nf < 4; nf++)
                    mma_f16(acc[mf][nf], ah[mf], bh[nf]);
        }
        if (++bufc == 3) bufc = 0;
    }
    __syncthreads();

    const float* qcs = (const float*)(smem + SM_QC);
    const float* W2s = (const float*)(smem + SM_W2);
    const float* P2s = (const float*)(smem + SM_P2);
    float* epart = (float*)(smem + SM_EPART);

    if (half == 0) {
#pragma unroll
        for (int mf = 0; mf < 2; mf++) {
#pragma unroll
            for (int rg = 0; rg < 2; rg++) {
                int rowl = m0 + mf * 16 + g4 + rg * 8;
                float p[8] = {0.f, 0.f, 0.f, 0.f, 0.f, 0.f, 0.f, 0.f};
#pragma unroll
                for (int nf = 0; nf < 4; nf++) {
#pragma unroll
                    for (int cp = 0; cp < 2; cp++) {
                        int lc = n0w + nf * 8 + t4 * 2 + cp;
                        float hv = fmaxf(acc[mf][nf][rg * 2 + cp] + qcs[lc], 0.f);
                        const float* w = W2s + lc * 8;
#pragma unroll
                        for (int k = 0; k < 8; k++) p[k] = fmaf(hv, w[k], p[k]);
                    }
                }
#pragma unroll
                for (int k = 0; k < 8; k++) {
                    p[k] += __shfl_xor_sync(0xffffffffu, p[k], 1);
                    p[k] += __shfl_xor_sync(0xffffffffu, p[k], 2);
                }
                if (t4 == 0) {
#pragma unroll
                    for (int k = 0; k < 8; k++)
                        epart[((size_t)wn * 64 + rowl) * 8 + k] = p[k];
                }
            }
        }
        __syncthreads();
        const float* b2s = (const float*)(smem + SM_B2);
        for (int t = tid; t < 64 * 8; t += 256) {
            int r = t >> 3, k = t & 7;
            float s = epart[(0 * 64 + r) * 8 + k] + epart[(1 * 64 + r) * 8 + k]
                    + epart[(2 * 64 + r) * 8 + k] + epart[(3 * 64 + r) * 8 + k];
            g_s[(size_t)(row0 + r) * K_ + k] = s + b2s[k];
        }
    } else {
#pragma unroll
        for (int mf = 0; mf < 2; mf++) {
#pragma unroll
            for (int rg = 0; rg < 2; rg++) {
                int rowl = m0 + mf * 16 + g4 + rg * 8;
                float p8 = 0.f;
#pragma unroll
                for (int nf = 0; nf < 4; nf++) {
#pragma unroll
                    for (int cp = 0; cp < 2; cp++) {
                        int lc = n0w + nf * 8 + t4 * 2 + cp;
                        float hv = fmaxf(acc[mf][nf][rg * 2 + cp] + qcs[lc], 0.f);
                        p8 = fmaf(hv, P2s[lc], p8);
                    }
                }
                p8 += __shfl_xor_sync(0xffffffffu, p8, 1);
                p8 += __shfl_xor_sync(0xffffffffu, p8, 2);
                if (t4 == 0) epart[(size_t)wn * 64 + rowl] = p8;
            }
        }
        __syncthreads();
        if (tid < 64) {
            float logit = epart[0 * 64 + tid] + epart[1 * 64 + tid]
                        + epart[2 * 64 + tid] + epart[3 * 64 + tid]
                        + *((const float*)(smem + SM_PB2));
            int row = row0 + tid;
            float factor = 1.f + 1.f / (1.f + expf(-logit)) + (float)labels[row];
            g_factor[row] = factor;
        }
    }
}

// ---------------- fused walk: amps -> spmm x2 -> final gather -> normalize ----------------
__device__ __forceinline__ void gather16h(const uint4* __restrict__ base,
                                          const int4* __restrict__ nb,
                                          float4& s0, float4& s1) {
    s0 = make_float4(0.f, 0.f, 0.f, 0.f);
    s1 = make_float4(0.f, 0.f, 0.f, 0.f);
#pragma unroll
    for (int j = 0; j < 4; j++) {
        int4 id = nb[j];
        acc_h(base[id.x], s0, s1);
        acc_h(base[id.y], s0, s1);
        acc_h(base[id.z], s0, s1);
        acc_h(base[id.w], s0, s1);
    }
}

__global__ __launch_bounds__(256, 4)
void walk_fused(const int* __restrict__ neighbors, float* __restrict__ out) {
    __shared__ float red[256];
    const int tid = threadIdx.x;
    const int node = blockIdx.x * 256 + tid;
    const int b = node >> 13;
    const int4* nb = (const int4*)(neighbors + (size_t)node * DEG_);

    // phase A: amps = s * factor
    {
        float f = g_factor[node];
        const float4* s = (const float4*)(g_s + (size_t)node * K_);
        float4 s0 = s[0], s1 = s[1];
        float4 a0 = make_float4(s0.x * f, s0.y * f, s0.z * f, s0.w * f);
        float4 a1 = make_float4(s1.x * f, s1.y * f, s1.z * f, s1.w * f);
        float4* o = (float4*)(g_amps + (size_t)node * K_);
        o[0] = a0;
        o[1] = a1;
        g_ampsh[node] = pack_h(a0, a1);
    }
    gridbar(0, WCTAS);

    // phase B: buf1 = amps ⊙ (A · ampsh)
    {
        float4 s0, s1;
        gather16h(g_ampsh + (size_t)b * N_, nb, s0, s1);
        const float4* am = (const float4*)(g_amps + (size_t)node * K_);
        float4 a0 = am[0], a1 = am[1];
        float4 o0 = make_float4(s0.x * a0.x * STSC, s0.y * a0.y * STSC,
                                s0.z * a0.z * STSC, s0.w * a0.w * STSC);
        float4 o1 = make_float4(s1.x * a1.x * STSC, s1.y * a1.y * STSC,
                                s1.z * a1.z * STSC, s1.w * a1.w * STSC);
        g_buf1h[node] = pack_h(o0, o1);
    }
    gridbar(1, WCTAS);

    // phase C: buf2 = amps ⊙ (A · buf1)
    {
        float4 s0, s1;
        gather16h(g_buf1h + (size_t)b * N_, nb, s0, s1);
        const float4* am = (const float4*)(g_amps + (size_t)node * K_);
        float4 a0 = am[0], a1 = am[1];
        float4 o0 = make_float4(s0.x * a0.x * STSC, s0.y * a0.y * STSC,
                                s0.z * a0.z * STSC, s0.w * a0.w * STSC);
        float4 o1 = make_float4(s1.x * a1.x * STSC, s1.y * a1.y * STSC,
                                s1.z * a1.z * STSC, s1.w * a1.w * STSC);
        g_buf2h[node] = pack_h(o0, o1);
    }
    gridbar(2, WCTAS);

    // phase D: v3 = A · buf2; absum + block sumsq partials
    float absum;
    {
        float4 s0, s1;
        gather16h(g_buf2h + (size_t)b * N_, nb, s0, s1);
        absum = fabsf(s0.x) + fabsf(s0.y) + fabsf(s0.z) + fabsf(s0.w)
              + fabsf(s1.x) + fabsf(s1.y) + fabsf(s1.z) + fabsf(s1.w);
        float ss = s0.x * s0.x + s0.y * s0.y + s0.z * s0.z + s0.w * s0.w
                 + s1.x * s1.x + s1.y * s1.y + s1.z * s1.z + s1.w * s1.w;
        red[tid] = ss;
        __syncthreads();
#pragma unroll
        for (int s = 128; s > 0; s >>= 1) {
            if (tid < s) red[tid] += red[tid + s];
            __syncthreads();
        }
        if (tid == 0) g_part[blockIdx.x] = red[0];
    }
    gridbar(3, WCTAS);

    // phase E: normalize
    {
        if (tid < 32) {
            float s = g_part[b * 32 + tid];
#pragma unroll
            for (int off = 16; off > 0; off >>= 1)
                s += __shfl_xor_sync(0xffffffffu, s, off);
            if (tid == 0) red[0] = s;
        }
        __syncthreads();
        float ss = red[0];
        float scale = (ss > 0.f) ? rsqrtf(ss) : 1.f;
        out[node] = absum * scale;
    }
}

// ---------------- launch ----------------
extern "C" void kernel_launch(void* const* d_in, const int* in_sizes, int n_in,
                              void* d_out, int out_size) {
    const float* q_embs    = (const float*)d_in[0];
    const float* emb       = (const float*)d_in[1];
    const int*   neighbors = (const int*)d_in[2];
    const int*   labels    = (const int*)d_in[3];
    const float* W1        = (const float*)d_in[4];
    const float* b1        = (const float*)d_in[5];
    const float* W2        = (const float*)d_in[6];
    const float* b2        = (const float*)d_in[7];
    const float* P1        = (const float*)d_in[8];
    const float* pb1       = (const float*)d_in[9];
    const float* P2        = (const float*)d_in[10];
    const float* pb2       = (const float*)d_in[11];
    float* out = (float*)d_out;

    cudaFuncSetAttribute(gemm_tc, cudaFuncAttributeMaxDynamicSharedMemorySize, SM_TOTAL);

    prep_all<<<113, 256>>>(q_embs, W1, b1, W2, b2, P1, pb1, P2, pb2);
    gemm_tc<<<(NODES / MTILE) * 2, 256, SM_TOTAL>>>(emb, labels);
    walk_fused<<<WCTAS, 256>>>(neighbors, out);
}